// round 14
// baseline (speedup 1.0000x reference)
#include <cuda_runtime.h>
#include <math.h>
#include <stdint.h>

// Problem dims (fixed by the reference)
#define BB   2
#define SS   2048
#define DD   1024
#define HH   16
#define DK   64
#define MM   (BB*SS)            // 4096 rows
#define TEMP_INV (1.0f/32.0f)   // 1/sqrt(1024)
#define LN_EPS 1e-5f

// Scratch (allocation-free rule: __device__ globals)
__device__ float g_kx   [(size_t)MM*DD];
__device__ float g_qx   [(size_t)MM*DD];
__device__ float g_vx   [(size_t)MM*DD];
__device__ float g_ctx  [(size_t)MM*DD];
__device__ float g_den  [(size_t)MM*DD];
__device__ float g_stats[(size_t)HH*BB*SS];   // 1/rowsum per (z, qrow)

// ---------------------------------------------------------------------------
// TF32 helpers
// ---------------------------------------------------------------------------
__device__ __forceinline__ uint32_t f2tf32(float x) {
    uint32_t r;
    asm("cvt.rna.tf32.f32 %0, %1;" : "=r"(r) : "f"(x));
    return r;
}

__device__ __forceinline__ void mma_tf32(float (&d)[4], const uint32_t (&a)[4],
                                         const uint32_t (&b)[2]) {
    asm volatile(
        "mma.sync.aligned.m16n8k8.row.col.f32.tf32.tf32.f32 "
        "{%0,%1,%2,%3}, {%4,%5,%6,%7}, {%8,%9}, {%0,%1,%2,%3};\n"
        : "+f"(d[0]), "+f"(d[1]), "+f"(d[2]), "+f"(d[3])
        : "r"(a[0]), "r"(a[1]), "r"(a[2]), "r"(a[3]),
          "r"(b[0]), "r"(b[1]));
}

// m16n8k8 fragment map (row.col), gid = lane>>2, tg = lane&3:
//  A: a0=(gid,tg) a1=(gid+8,tg) a2=(gid,tg+4) a3=(gid+8,tg+4)   [row=m,col=k]
//  B: b0=(k=tg, n=gid) b1=(k=tg+4, n=gid)
//  C: c0=(gid, tg*2) c1=(gid, tg*2+1) c2=(gid+8, tg*2) c3=(gid+8, tg*2+1)

// ---------------------------------------------------------------------------
// 128x64 TF32 GEMM body: C = A @ W^T + bias (optional ReLU).
// BK=16, 256 threads (8 warps as 2x4), warp tile 64x16, acc 32 regs.
// Lower register pressure -> 3 CTAs/SM (was 2 at 128x128/124 regs).
// ---------------------------------------------------------------------------
template <bool RELU>
__device__ __forceinline__
void gemm_body64(const float* __restrict__ A, const float* __restrict__ W,
                 const float* __restrict__ bias, float* __restrict__ C,
                 int Ndim, int Kdim, int row0, int col0,
                 uint32_t (*As)[128*20], uint32_t (*Bs)[64*20])
{
    const int tid  = threadIdx.x;
    const int lane = tid & 31;
    const int warp = tid >> 5;
    const int wm   = (warp >> 2) * 64;   // 0 or 64
    const int wn   = (warp &  3) * 16;   // 0,16,32,48
    const int gid  = lane >> 2;
    const int tg   = lane & 3;

    float acc[4][2][4] = {};

    // A: 128 rows x 16 k = 512 float4 -> 2/thread;  W: 64 rows -> 1/thread
    float4 pa[2], pb;
#pragma unroll
    for (int i = 0; i < 2; i++) {
        const int idx = tid + i * 256;        // 0..511
        const int r   = idx >> 2;             // 0..127
        const int k4  = (idx & 3) * 4;        // 0,4,8,12
        pa[i] = *(const float4*)&A[(size_t)(row0 + r) * Kdim + k4];
    }
    {
        const int r  = tid >> 2;              // 0..63
        const int k4 = (tid & 3) * 4;
        pb = *(const float4*)&W[(size_t)(col0 + r) * Kdim + k4];
    }
#pragma unroll
    for (int i = 0; i < 2; i++) {
        const int idx = tid + i * 256;
        const int r   = idx >> 2;
        const int k4  = (idx & 3) * 4;
        *(uint4*)&As[0][r * 20 + k4] = make_uint4(f2tf32(pa[i].x), f2tf32(pa[i].y), f2tf32(pa[i].z), f2tf32(pa[i].w));
    }
    {
        const int r  = tid >> 2;
        const int k4 = (tid & 3) * 4;
        *(uint4*)&Bs[0][r * 20 + k4] = make_uint4(f2tf32(pb.x), f2tf32(pb.y), f2tf32(pb.z), f2tf32(pb.w));
    }
    __syncthreads();

    int p = 0;
    for (int k0 = 0; k0 < Kdim; k0 += 16) {
        const bool more = (k0 + 16 < Kdim);
        if (more) {
#pragma unroll
            for (int i = 0; i < 2; i++) {
                const int idx = tid + i * 256;
                const int r   = idx >> 2;
                const int k4  = (idx & 3) * 4;
                pa[i] = *(const float4*)&A[(size_t)(row0 + r) * Kdim + k0 + 16 + k4];
            }
            {
                const int r  = tid >> 2;
                const int k4 = (tid & 3) * 4;
                pb = *(const float4*)&W[(size_t)(col0 + r) * Kdim + k0 + 16 + k4];
            }
        }
#pragma unroll
        for (int s = 0; s < 2; s++) {
            const int ko = s * 8;
            uint32_t a[4][4], b[2][2];
#pragma unroll
            for (int mt = 0; mt < 4; mt++) {
                const uint32_t* base = &As[p][(wm + mt*16 + gid) * 20 + ko + tg];
                a[mt][0] = base[0];
                a[mt][1] = base[8*20];
                a[mt][2] = base[4];
                a[mt][3] = base[8*20 + 4];
            }
#pragma unroll
            for (int nt = 0; nt < 2; nt++) {
                const uint32_t* base = &Bs[p][(wn + nt*8 + gid) * 20 + ko + tg];
                b[nt][0] = base[0];
                b[nt][1] = base[4];
            }
#pragma unroll
            for (int mt = 0; mt < 4; mt++)
#pragma unroll
                for (int nt = 0; nt < 2; nt++)
                    mma_tf32(acc[mt][nt], a[mt], b[nt]);
        }
        if (more) {
            const int q = p ^ 1;
#pragma unroll
            for (int i = 0; i < 2; i++) {
                const int idx = tid + i * 256;
                const int r   = idx >> 2;
                const int k4  = (idx & 3) * 4;
                *(uint4*)&As[q][r * 20 + k4] = make_uint4(f2tf32(pa[i].x), f2tf32(pa[i].y), f2tf32(pa[i].z), f2tf32(pa[i].w));
            }
            {
                const int r  = tid >> 2;
                const int k4 = (tid & 3) * 4;
                *(uint4*)&Bs[q][r * 20 + k4] = make_uint4(f2tf32(pb.x), f2tf32(pb.y), f2tf32(pb.z), f2tf32(pb.w));
            }
            __syncthreads();
            p = q;
        }
    }

#pragma unroll
    for (int mt = 0; mt < 4; mt++) {
        const int r1 = row0 + wm + mt*16 + gid;
        const int r2 = r1 + 8;
#pragma unroll
        for (int nt = 0; nt < 2; nt++) {
            const int c = col0 + wn + nt*8 + tg*2;
            const float b0 = bias[c], b1 = bias[c+1];
            float2 v1 = make_float2(acc[mt][nt][0] + b0, acc[mt][nt][1] + b1);
            float2 v2 = make_float2(acc[mt][nt][2] + b0, acc[mt][nt][3] + b1);
            if (RELU) {
                v1.x = fmaxf(v1.x, 0.f); v1.y = fmaxf(v1.y, 0.f);
                v2.x = fmaxf(v2.x, 0.f); v2.y = fmaxf(v2.y, 0.f);
            }
            *(float2*)&C[(size_t)r1 * Ndim + c] = v1;
            *(float2*)&C[(size_t)r2 * Ndim + c] = v2;
        }
    }
}

// ---------------------------------------------------------------------------
// All three projections in ONE launch: blockIdx.z selects {K,Q,V}.
// Grid (16, 32, 3) = 1536 CTAs of 128x64.
// ---------------------------------------------------------------------------
__global__ __launch_bounds__(256)
void proj_tf32(const float* __restrict__ k, const float* __restrict__ q,
               const float* __restrict__ wkw, const float* __restrict__ wkb,
               const float* __restrict__ wqw, const float* __restrict__ wqb,
               const float* __restrict__ wvw, const float* __restrict__ wvb,
               float* __restrict__ kx, float* __restrict__ qx,
               float* __restrict__ vx)
{
    __shared__ uint32_t As[2][128*20];
    __shared__ uint32_t Bs[2][64*20];

    const int zz = blockIdx.z;
    const float* A    = (zz == 1) ? q   : k;
    const float* W    = (zz == 0) ? wkw : (zz == 1) ? wqw : wvw;
    const float* bias = (zz == 0) ? wkb : (zz == 1) ? wqb : wvb;
    float*       C    = (zz == 0) ? kx  : (zz == 1) ? qx  : vx;

    gemm_body64<false>(A, W, bias, C, DD, DD,
                       blockIdx.y * 128, blockIdx.x * 64, As, Bs);
}

// ---------------------------------------------------------------------------
// Dense + ReLU (single GEMM).  Grid (16, 32) = 512 CTAs of 128x64.
// ---------------------------------------------------------------------------
__global__ __launch_bounds__(256)
void dense_tf32(const float* __restrict__ A, const float* __restrict__ W,
                const float* __restrict__ bias, float* __restrict__ C)
{
    __shared__ uint32_t As[2][128*20];
    __shared__ uint32_t Bs[2][64*20];
    gemm_body64<true>(A, W, bias, C, DD, DD,
                      blockIdx.y * 128, blockIdx.x * 64, As, Bs);
}

// ---------------------------------------------------------------------------
// PASS A: row_sums — identical MMA/exp math to score_av, but NO attn stores.
// K tile prefetched one iteration ahead (register pipeline).
// ---------------------------------------------------------------------------
__global__ __launch_bounds__(256)
void row_sums(const float* __restrict__ qx, const float* __restrict__ kx,
              float* __restrict__ stats)
{
    __shared__ uint32_t Qs[64*68];
    __shared__ uint32_t Ks[64*68];
    __shared__ float rowsum[64];

    const int z = blockIdx.z;
    const int h = z >> 1;             // B == 2
    const int b = z & 1;
    const float* Qb = qx + (size_t)b * SS * DD + h * DK;
    const float* Kb = kx + (size_t)b * SS * DD + h * DK;

    const int tid  = threadIdx.x;
    const int lane = tid & 31;
    const int warp = tid >> 5;
    const int wm   = (warp >> 2) * 32;   // 0 or 32
    const int wn   = (warp &  3) * 16;   // 0,16,32,48
    const int gid  = lane >> 2;
    const int tg   = lane & 3;
    const int row0 = blockIdx.y * 64;

    if (tid < 64) rowsum[tid] = 0.0f;

#pragma unroll
    for (int i = 0; i < 4; i++) {
        const int idx = tid + i * 256;      // 0..1023
        const int r   = idx >> 4;           // 0..63
        const int k4  = (idx & 15) * 4;     // 0..60
        float4 v = *(const float4*)&Qb[(size_t)(row0 + r) * DD + k4];
        *(uint4*)&Qs[r * 68 + k4] = make_uint4(f2tf32(v.x), f2tf32(v.y), f2tf32(v.z), f2tf32(v.w));
    }

    // preload K tile 0 into registers
    float4 kf[4];
#pragma unroll
    for (int i = 0; i < 4; i++) {
        const int idx = tid + i * 256;
        const int r   = idx >> 4;
        const int k4  = (idx & 15) * 4;
        kf[i] = *(const float4*)&Kb[(size_t)r * DD + k4];
    }

    for (int ct = 0; ct < SS / 64; ct++) {
        if (ct) __syncthreads();            // prev MMA reads of Ks done
#pragma unroll
        for (int i = 0; i < 4; i++) {
            const int idx = tid + i * 256;
            const int r   = idx >> 4;
            const int k4  = (idx & 15) * 4;
            *(uint4*)&Ks[r * 68 + k4] = make_uint4(f2tf32(kf[i].x), f2tf32(kf[i].y), f2tf32(kf[i].z), f2tf32(kf[i].w));
        }
        if (ct + 1 < SS / 64) {             // prefetch next K tile
#pragma unroll
            for (int i = 0; i < 4; i++) {
                const int idx = tid + i * 256;
                const int r   = idx >> 4;
                const int k4  = (idx & 15) * 4;
                kf[i] = *(const float4*)&Kb[(size_t)((ct + 1) * 64 + r) * DD + k4];
            }
        }
        __syncthreads();

        float acc[2][2][4] = {};
#pragma unroll
        for (int s = 0; s < 8; s++) {
            const int ko = s * 8;
            uint32_t a[2][4], bf[2][2];
#pragma unroll
            for (int mt = 0; mt < 2; mt++) {
                const uint32_t* base = &Qs[(wm + mt*16 + gid) * 68 + ko + tg];
                a[mt][0] = base[0];
                a[mt][1] = base[8*68];
                a[mt][2] = base[4];
                a[mt][3] = base[8*68 + 4];
            }
#pragma unroll
            for (int nt = 0; nt < 2; nt++) {
                const uint32_t* base = &Ks[(wn + nt*8 + gid) * 68 + ko + tg];
                bf[nt][0] = base[0];
                bf[nt][1] = base[4];
            }
#pragma unroll
            for (int mt = 0; mt < 2; mt++)
#pragma unroll
                for (int nt = 0; nt < 2; nt++)
                    mma_tf32(acc[mt][nt], a[mt], bf[nt]);
        }

#pragma unroll
        for (int mt = 0; mt < 2; mt++) {
            const int r1 = wm + mt*16 + gid;   // local row
            const int r2 = r1 + 8;
            float s1 = 0.0f, s2 = 0.0f;
#pragma unroll
            for (int nt = 0; nt < 2; nt++) {
                s1 += __expf(acc[mt][nt][0] * TEMP_INV) + __expf(acc[mt][nt][1] * TEMP_INV);
                s2 += __expf(acc[mt][nt][2] * TEMP_INV) + __expf(acc[mt][nt][3] * TEMP_INV);
            }
            s1 += __shfl_xor_sync(0xffffffffu, s1, 1);
            s1 += __shfl_xor_sync(0xffffffffu, s1, 2);
            s2 += __shfl_xor_sync(0xffffffffu, s2, 1);
            s2 += __shfl_xor_sync(0xffffffffu, s2, 2);
            if (tg == 0) {
                atomicAdd(&rowsum[r1], s1);
                atomicAdd(&rowsum[r2], s2);
            }
        }
    }
    __syncthreads();
    if (tid < 64)
        stats[(size_t)z * SS + row0 + tid] = 1.0f / rowsum[tid];
}

// ---------------------------------------------------------------------------
// PASS B: score_av — recompute identical s, scale by known inv, write the
// NORMALIZED attn exactly once, stage P in smem (ALIASED onto Ks — Ks is
// dead after the QK MMA), fuse P@V into ctx.
// K tile prefetched one iter ahead; V loaded at iter top, stored mid-iter
// (latency hidden under QK+exp). Dynamic smem 53504 B.
// ---------------------------------------------------------------------------
#define SAV_SMEM_BYTES 53504
__global__ __launch_bounds__(256)
void score_av(const float* __restrict__ qx, const float* __restrict__ kx,
              const float* __restrict__ stats, const float* __restrict__ vx,
              float* __restrict__ attn, float* __restrict__ ctx)
{
    extern __shared__ uint32_t sm[];
    uint32_t* Qs  = sm;                  // 64*68 = 4352 words
    uint32_t* Ks  = sm + 4352;           // 4352 (Ps aliases this region)
    uint32_t* Ps  = sm + 4352;           // alias of Ks
    uint32_t* Vs  = sm + 8704;           // 64*72 = 4608
    float* inv_s  = (float*)(sm + 13312);// 64 words  (total 13376 w = 53504 B)

    const int z = blockIdx.z;
    const int h = z >> 1;
    const int b = z & 1;
    const float* Qb = qx + (size_t)b * SS * DD + h * DK;
    const float* Kb = kx + (size_t)b * SS * DD + h * DK;
    const float* Vb = vx + (size_t)b * SS * DD + h * DK;
    float* Ab = attn + (size_t)z * SS * SS;
    float* Cb = ctx + (size_t)b * SS * DD + h * DK;

    const int tid  = threadIdx.x;
    const int lane = tid & 31;
    const int warp = tid >> 5;
    const int wm   = (warp >> 2) * 32;   // 0 or 32
    const int wn   = (warp &  3) * 16;   // 0,16,32,48
    const int gid  = lane >> 2;
    const int tg   = lane & 3;
    const int row0 = blockIdx.y * 64;

    // load Q strip + inv
#pragma unroll
    for (int i = 0; i < 4; i++) {
        const int idx = tid + i * 256;
        const int r   = idx >> 4;
        const int k4  = (idx & 15) * 4;
        float4 v = *(const float4*)&Qb[(size_t)(row0 + r) * DD + k4];
        *(uint4*)&Qs[r * 68 + k4] = make_uint4(f2tf32(v.x), f2tf32(v.y), f2tf32(v.z), f2tf32(v.w));
    }
    if (tid < 64) inv_s[tid] = stats[(size_t)z * SS + row0 + tid];

    // preload K tile 0
    float4 kf[4];
#pragma unroll
    for (int i = 0; i < 4; i++) {
        const int idx = tid + i * 256;
        const int r   = idx >> 4;
        const int k4  = (idx & 15) * 4;
        kf[i] = *(const float4*)&Kb[(size_t)r * DD + k4];
    }

    float cacc[2][2][4] = {};

    for (int ct = 0; ct < SS / 64; ct++) {
        if (ct) __syncthreads();   // prev AV reads of Ps(=Ks) & Vs done
        // store K tile (from prefetch regs)
#pragma unroll
        for (int i = 0; i < 4; i++) {
            const int idx = tid + i * 256;
            const int r   = idx >> 4;
            const int k4  = (idx & 15) * 4;
            *(uint4*)&Ks[r * 68 + k4] = make_uint4(f2tf32(kf[i].x), f2tf32(kf[i].y), f2tf32(kf[i].z), f2tf32(kf[i].w));
        }
        // load V tile for THIS iter (consumed mid-iter, latency hidden)
        float4 vf[4];
#pragma unroll
        for (int i = 0; i < 4; i++) {
            const int idx = tid + i * 256;
            const int r   = idx >> 4;
            const int k4  = (idx & 15) * 4;
            vf[i] = *(const float4*)&Vb[(size_t)(ct * 64 + r) * DD + k4];
        }
        // prefetch K tile for NEXT iter
        if (ct + 1 < SS / 64) {
#pragma unroll
            for (int i = 0; i < 4; i++) {
                const int idx = tid + i * 256;
                const int r   = idx >> 4;
                const int k4  = (idx & 15) * 4;
                kf[i] = *(const float4*)&Kb[(size_t)((ct + 1) * 64 + r) * DD + k4];
            }
        }
        __syncthreads();   // Ks ready (ct=0: Qs/inv also)

        // QK^T (identical fragment/MMA order to row_sums -> identical s)
        float sacc[2][2][4] = {};
#pragma unroll
        for (int s = 0; s < 8; s++) {
            const int ko = s * 8;
            uint32_t a[2][4], bf[2][2];
#pragma unroll
            for (int mt = 0; mt < 2; mt++) {
                const uint32_t* base = &Qs[(wm + mt*16 + gid) * 68 + ko + tg];
                a[mt][0] = base[0];
                a[mt][1] = base[8*68];
                a[mt][2] = base[4];
                a[mt][3] = base[8*68 + 4];
            }
#pragma unroll
            for (int nt = 0; nt < 2; nt++) {
                const uint32_t* base = &Ks[(wn + nt*8 + gid) * 68 + ko + tg];
                bf[nt][0] = base[0];
                bf[nt][1] = base[4];
            }
#pragma unroll
            for (int mt = 0; mt < 2; mt++)
#pragma unroll
                for (int nt = 0; nt < 2; nt++)
                    mma_tf32(sacc[mt][nt], a[mt], bf[nt]);
        }

        // exp * inv -> normalized p; STG attn once (keep p in regs)
        float pv[2][2][4];
#pragma unroll
        for (int mt = 0; mt < 2; mt++) {
            const int r1 = wm + mt*16 + gid;
            const int r2 = r1 + 8;
            const float iv1 = inv_s[r1];
            const float iv2 = inv_s[r2];
#pragma unroll
            for (int nt = 0; nt < 2; nt++) {
                pv[mt][nt][0] = __expf(sacc[mt][nt][0] * TEMP_INV) * iv1;
                pv[mt][nt][1] = __expf(sacc[mt][nt][1] * TEMP_INV) * iv1;
                pv[mt][nt][2] = __expf(sacc[mt][nt][2] * TEMP_INV) * iv2;
                pv[mt][nt][3] = __expf(sacc[mt][nt][3] * TEMP_INV) * iv2;
                const int c = wn + nt*8 + tg*2;
                const int gc = ct * 64 + c;
                *(float2*)&Ab[(size_t)(row0 + r1) * SS + gc] = make_float2(pv[mt][nt][0], pv[mt][nt][1]);
                *(float2*)&Ab[(size_t)(row0 + r2) * SS + gc] = make_float2(pv[mt][nt][2], pv[mt][nt][3]);
            }
        }
        __syncthreads();   // all QK reads of Ks done -> safe to overwrite as Ps

        // stage P (into Ks region) and V tile
#pragma unroll
        for (int mt = 0; mt < 2; mt++) {
            const int r1 = wm + mt*16 + gid;
            const int r2 = r1 + 8;
#pragma unroll
            for (int nt = 0; nt < 2; nt++) {
                const int c = wn + nt*8 + tg*2;
                *(uint2*)&Ps[r1 * 68 + c] = make_uint2(f2tf32(pv[mt][nt][0]), f2tf32(pv[mt][nt][1]));
                *(uint2*)&Ps[r2 * 68 + c] = make_uint2(f2tf32(pv[mt][nt][2]), f2tf32(pv[mt][nt][3]));
            }
        }
#pragma unroll
        for (int i = 0; i < 4; i++) {
            const int idx = tid + i * 256;
            const int r   = idx >> 4;
            const int k4  = (idx & 15) * 4;
            *(uint4*)&Vs[r * 72 + k4] = make_uint4(f2tf32(vf[i].x), f2tf32(vf[i].y), f2tf32(vf[i].z), f2tf32(vf[i].w));
        }
        __syncthreads();   // Ps & Vs ready

        // AV: ctx += P(64q x 64k) @ V(64k x 64d); warp tile 32q x 16d
#pragma unroll
        for (int s = 0; s < 8; s++) {
            const int ko = s * 8;
            uint32_t a[2][4], bf[2][2];
#pragma unroll
            for (int mt = 0; mt < 2; mt++) {
                const uint32_t* base = &Ps[(wm + mt*16 + gid) * 68 + ko + tg];
                a[mt][0] = base[0];
                a[mt][1] = base[8*68];
                a[mt][2] = base[4];
                a[mt][3] = base[8*68 + 4];
            }
#pragma unroll
            for (int nt = 0; nt < 2; nt++) {
                const uint32_t* base = &Vs[(ko + tg) * 72 + wn + nt*8 + gid];
                bf[nt][0] = base[0];
                bf[nt][1] = base[4*72];
            }
#pragma unroll
            for (int mt = 0; mt < 2; mt++)
#pragma unroll
                for (int nt = 0; nt < 2; nt++)
                    mma_tf32(cacc[mt][nt], a[mt], bf[nt]);
        }
    }

    // write ctx
#pragma unroll
    for (int mt = 0; mt < 2; mt++) {
        const int r1 = row0 + wm + mt*16 + gid;
        const int r2 = r1 + 8;
#pragma unroll
        for (int nt = 0; nt < 2; nt++) {
            const int c = wn + nt*8 + tg*2;
            *(float2*)&Cb[(size_t)r1 * DD + c] = make_float2(cacc[mt][nt][0], cacc[mt][nt][1]);
            *(float2*)&Cb[(size_t)r2 * DD + c] = make_float2(cacc[mt][nt][2], cacc[mt][nt][3]);
        }
    }
}

// ---------------------------------------------------------------------------
// LayerNorm over last dim (1024). One block per row, warp-shuffle reductions.
// ---------------------------------------------------------------------------
__global__ __launch_bounds__(256)
void ln_kernel(const float* __restrict__ x, const float* __restrict__ g,
               const float* __restrict__ bta, float* __restrict__ out)
{
    const float* p = x + (size_t)blockIdx.x * DD;
    float* o = out + (size_t)blockIdx.x * DD;
    const int t = threadIdx.x;
    const int lane = t & 31, warp = t >> 5;
    __shared__ float reds[8], redq[8];

    float v[4];
    {
        float4 v0 = *(const float4*)&p[t*4];
        v[0]=v0.x; v[1]=v0.y; v[2]=v0.z; v[3]=v0.w;
    }
    float s = v[0]+v[1]+v[2]+v[3];
    float sq = v[0]*v[0]+v[1]*v[1]+v[2]*v[2]+v[3]*v[3];
#pragma unroll
    for (int off = 16; off > 0; off >>= 1) {
        s  += __shfl_xor_sync(0xffffffffu, s,  off);
        sq += __shfl_xor_sync(0xffffffffu, sq, off);
    }
    if (lane == 0) { reds[warp] = s; redq[warp] = sq; }
    __syncthreads();
    s = 0.0f; sq = 0.0f;
#pragma unroll
    for (int w = 0; w < 8; w++) { s += reds[w]; sq += redq[w]; }

    const float mean = s * (1.0f / DD);
    const float var  = sq * (1.0f / DD) - mean * mean;
    const float inv  = rsqrtf(var + LN_EPS);

    float4 gv = *(const float4*)&g[t*4];
    float4 bv = *(const float4*)&bta[t*4];
    float4 ov;
    ov.x = (v[0] - mean) * inv * gv.x + bv.x;
    ov.y = (v[1] - mean) * inv * gv.y + bv.y;
    ov.z = (v[2] - mean) * inv * gv.z + bv.z;
    ov.w = (v[3] - mean) * inv * gv.w + bv.w;
    *(float4*)&o[t*4] = ov;
}

// ---------------------------------------------------------------------------
extern "C" void kernel_launch(void* const* d_in, const int* in_sizes, int n_in,
                              void* d_out, int out_size)
{
    const float* k    = (const float*)d_in[0];
    const float* q    = (const float*)d_in[1];
    const float* wkw  = (const float*)d_in[2];
    const float* wkb  = (const float*)d_in[3];
    const float* wqw  = (const float*)d_in[4];
    const float* wqb  = (const float*)d_in[5];
    const float* wvw  = (const float*)d_in[6];
    const float* wvb  = (const float*)d_in[7];
    const float* dw   = (const float*)d_in[8];
    const float* db   = (const float*)d_in[9];
    const float* lng  = (const float*)d_in[10];
    const float* lnb  = (const float*)d_in[11];

    float* out  = (float*)d_out;                       // [B, S, D]
    float* attn = out + (size_t)MM * DD;               // [H*B, S, S]

    float *p_kx, *p_qx, *p_vx, *p_ctx, *p_den, *p_st;
    cudaGetSymbolAddress((void**)&p_kx,  g_kx);
    cudaGetSymbolAddress((void**)&p_qx,  g_qx);
    cudaGetSymbolAddress((void**)&p_vx,  g_vx);
    cudaGetSymbolAddress((void**)&p_ctx, g_ctx);
    cudaGetSymbolAddress((void**)&p_den, g_den);
    cudaGetSymbolAddress((void**)&p_st,  g_stats);

    // Idempotent, capture-safe; no static guard (harness forbids them).
    cudaFuncSetAttribute(score_av, cudaFuncAttributeMaxDynamicSharedMemorySize,
                         SAV_SMEM_BYTES);

    dim3 gProj(DD / 64, MM / 128, 3);                  // 16 x 32 x 3 = 1536 CTAs

    proj_tf32<<<gProj, 256>>>(k, q, wkw, wkb, wqw, wqb, wvw, wvb,
                              p_kx, p_qx, p_vx);

    row_sums<<<dim3(1, SS/64, HH*BB), 256>>>(p_qx, p_kx, p_st);
    score_av<<<dim3(1, SS/64, HH*BB), 256, SAV_SMEM_BYTES>>>(
        p_qx, p_kx, p_st, p_vx, attn, p_ctx);

    dense_tf32<<<dim3(DD/64, MM/128), 256>>>(p_ctx, dw, db, p_den);
    ln_kernel<<<MM, 256>>>(p_den, lng, lnb, out);
}

// round 15
// speedup vs baseline: 1.1053x; 1.1053x over previous
#include <cuda_runtime.h>
#include <math.h>
#include <stdint.h>

// Problem dims (fixed by the reference)
#define BB   2
#define SS   2048
#define DD   1024
#define HH   16
#define DK   64
#define MM   (BB*SS)            // 4096 rows
#define TEMP_INV (1.0f/32.0f)   // 1/sqrt(1024)
#define LN_EPS 1e-5f

// Scratch (allocation-free rule: __device__ globals)
__device__ float g_kx   [(size_t)MM*DD];
__device__ float g_qx   [(size_t)MM*DD];
__device__ float g_vx   [(size_t)MM*DD];
__device__ float g_ctx  [(size_t)MM*DD];
__device__ float g_den  [(size_t)MM*DD];
__device__ float g_stats[(size_t)HH*BB*SS];   // 1/rowsum per (z, qrow)

// ---------------------------------------------------------------------------
// TF32 helpers
// ---------------------------------------------------------------------------
__device__ __forceinline__ uint32_t f2tf32(float x) {
    uint32_t r;
    asm("cvt.rna.tf32.f32 %0, %1;" : "=r"(r) : "f"(x));
    return r;
}

__device__ __forceinline__ void mma_tf32(float (&d)[4], const uint32_t (&a)[4],
                                         const uint32_t (&b)[2]) {
    asm volatile(
        "mma.sync.aligned.m16n8k8.row.col.f32.tf32.tf32.f32 "
        "{%0,%1,%2,%3}, {%4,%5,%6,%7}, {%8,%9}, {%0,%1,%2,%3};\n"
        : "+f"(d[0]), "+f"(d[1]), "+f"(d[2]), "+f"(d[3])
        : "r"(a[0]), "r"(a[1]), "r"(a[2]), "r"(a[3]),
          "r"(b[0]), "r"(b[1]));
}

// m16n8k8 fragment map (row.col), gid = lane>>2, tg = lane&3:
//  A: a0=(gid,tg) a1=(gid+8,tg) a2=(gid,tg+4) a3=(gid+8,tg+4)   [row=m,col=k]
//  B: b0=(k=tg, n=gid) b1=(k=tg+4, n=gid)
//  C: c0=(gid, tg*2) c1=(gid, tg*2+1) c2=(gid+8, tg*2) c3=(gid+8, tg*2+1)

// ---------------------------------------------------------------------------
// Core 128x128 TF32 GEMM body: C = A @ W^T + bias (optional ReLU).
// Block tile 128x128, BK=16, 256 threads (8 warps as 2x4), warp tile 64x32.
// (REVERTED to the measured-best round-11 config: dense 84.7us, tensor 32.8%.
//  The 128x64 split regressed: 2.5 LDS/MMA vs 1.5 here — smem-issue-bound.)
// ---------------------------------------------------------------------------
template <bool RELU>
__device__ __forceinline__
void gemm_body(const float* __restrict__ A, const float* __restrict__ W,
               const float* __restrict__ bias, float* __restrict__ C,
               int Ndim, int Kdim, int row0, int col0,
               uint32_t (*As)[128*20], uint32_t (*Bs)[128*20])
{
    const int tid  = threadIdx.x;
    const int lane = tid & 31;
    const int warp = tid >> 5;
    const int wm   = (warp >> 2) * 64;   // 0 or 64
    const int wn   = (warp &  3) * 32;   // 0,32,64,96
    const int gid  = lane >> 2;
    const int tg   = lane & 3;

    float acc[4][4][4] = {};

    float4 pa[2], pb[2];
#pragma unroll
    for (int i = 0; i < 2; i++) {
        const int idx = tid + i * 256;        // 0..511
        const int r   = idx >> 2;             // 0..127
        const int k4  = (idx & 3) * 4;        // 0,4,8,12
        pa[i] = *(const float4*)&A[(size_t)(row0 + r) * Kdim + k4];
        pb[i] = *(const float4*)&W[(size_t)(col0 + r) * Kdim + k4];
    }
#pragma unroll
    for (int i = 0; i < 2; i++) {
        const int idx = tid + i * 256;
        const int r   = idx >> 2;
        const int k4  = (idx & 3) * 4;
        *(uint4*)&As[0][r * 20 + k4] = make_uint4(f2tf32(pa[i].x), f2tf32(pa[i].y), f2tf32(pa[i].z), f2tf32(pa[i].w));
        *(uint4*)&Bs[0][r * 20 + k4] = make_uint4(f2tf32(pb[i].x), f2tf32(pb[i].y), f2tf32(pb[i].z), f2tf32(pb[i].w));
    }
    __syncthreads();

    int p = 0;
    for (int k0 = 0; k0 < Kdim; k0 += 16) {
        const bool more = (k0 + 16 < Kdim);
        if (more) {
#pragma unroll
            for (int i = 0; i < 2; i++) {
                const int idx = tid + i * 256;
                const int r   = idx >> 2;
                const int k4  = (idx & 3) * 4;
                pa[i] = *(const float4*)&A[(size_t)(row0 + r) * Kdim + k0 + 16 + k4];
                pb[i] = *(const float4*)&W[(size_t)(col0 + r) * Kdim + k0 + 16 + k4];
            }
        }
#pragma unroll
        for (int s = 0; s < 2; s++) {
            const int ko = s * 8;
            uint32_t a[4][4], b[4][2];
#pragma unroll
            for (int mt = 0; mt < 4; mt++) {
                const uint32_t* base = &As[p][(wm + mt*16 + gid) * 20 + ko + tg];
                a[mt][0] = base[0];
                a[mt][1] = base[8*20];
                a[mt][2] = base[4];
                a[mt][3] = base[8*20 + 4];
            }
#pragma unroll
            for (int nt = 0; nt < 4; nt++) {
                const uint32_t* base = &Bs[p][(wn + nt*8 + gid) * 20 + ko + tg];
                b[nt][0] = base[0];
                b[nt][1] = base[4];
            }
#pragma unroll
            for (int mt = 0; mt < 4; mt++)
#pragma unroll
                for (int nt = 0; nt < 4; nt++)
                    mma_tf32(acc[mt][nt], a[mt], b[nt]);
        }
        if (more) {
            const int q = p ^ 1;
#pragma unroll
            for (int i = 0; i < 2; i++) {
                const int idx = tid + i * 256;
                const int r   = idx >> 2;
                const int k4  = (idx & 3) * 4;
                *(uint4*)&As[q][r * 20 + k4] = make_uint4(f2tf32(pa[i].x), f2tf32(pa[i].y), f2tf32(pa[i].z), f2tf32(pa[i].w));
                *(uint4*)&Bs[q][r * 20 + k4] = make_uint4(f2tf32(pb[i].x), f2tf32(pb[i].y), f2tf32(pb[i].z), f2tf32(pb[i].w));
            }
            __syncthreads();
            p = q;
        }
    }

#pragma unroll
    for (int mt = 0; mt < 4; mt++) {
        const int r1 = row0 + wm + mt*16 + gid;
        const int r2 = r1 + 8;
#pragma unroll
        for (int nt = 0; nt < 4; nt++) {
            const int c = col0 + wn + nt*8 + tg*2;
            const float b0 = bias[c], b1 = bias[c+1];
            float2 v1 = make_float2(acc[mt][nt][0] + b0, acc[mt][nt][1] + b1);
            float2 v2 = make_float2(acc[mt][nt][2] + b0, acc[mt][nt][3] + b1);
            if (RELU) {
                v1.x = fmaxf(v1.x, 0.f); v1.y = fmaxf(v1.y, 0.f);
                v2.x = fmaxf(v2.x, 0.f); v2.y = fmaxf(v2.y, 0.f);
            }
            *(float2*)&C[(size_t)r1 * Ndim + c] = v1;
            *(float2*)&C[(size_t)r2 * Ndim + c] = v2;
        }
    }
}

// ---------------------------------------------------------------------------
// All three projections in ONE launch: blockIdx.z selects {K,Q,V}.
// ---------------------------------------------------------------------------
__global__ __launch_bounds__(256)
void proj_tf32(const float* __restrict__ k, const float* __restrict__ q,
               const float* __restrict__ wkw, const float* __restrict__ wkb,
               const float* __restrict__ wqw, const float* __restrict__ wqb,
               const float* __restrict__ wvw, const float* __restrict__ wvb,
               float* __restrict__ kx, float* __restrict__ qx,
               float* __restrict__ vx)
{
    __shared__ uint32_t As[2][128*20];
    __shared__ uint32_t Bs[2][128*20];

    const int zz = blockIdx.z;
    const float* A    = (zz == 1) ? q   : k;
    const float* W    = (zz == 0) ? wkw : (zz == 1) ? wqw : wvw;
    const float* bias = (zz == 0) ? wkb : (zz == 1) ? wqb : wvb;
    float*       C    = (zz == 0) ? kx  : (zz == 1) ? qx  : vx;

    gemm_body<false>(A, W, bias, C, DD, DD,
                     blockIdx.y * 128, blockIdx.x * 128, As, Bs);
}

// ---------------------------------------------------------------------------
// Dense + ReLU (single GEMM).
// ---------------------------------------------------------------------------
__global__ __launch_bounds__(256)
void dense_tf32(const float* __restrict__ A, const float* __restrict__ W,
                const float* __restrict__ bias, float* __restrict__ C)
{
    __shared__ uint32_t As[2][128*20];
    __shared__ uint32_t Bs[2][128*20];
    gemm_body<true>(A, W, bias, C, DD, DD,
                    blockIdx.y * 128, blockIdx.x * 128, As, Bs);
}

// ---------------------------------------------------------------------------
// PASS A: row_sums — identical MMA/exp math to score_av, but NO attn stores.
// K tile prefetched one iteration ahead (register pipeline).
// ---------------------------------------------------------------------------
__global__ __launch_bounds__(256)
void row_sums(const float* __restrict__ qx, const float* __restrict__ kx,
              float* __restrict__ stats)
{
    __shared__ uint32_t Qs[64*68];
    __shared__ uint32_t Ks[64*68];
    __shared__ float rowsum[64];

    const int z = blockIdx.z;
    const int h = z >> 1;             // B == 2
    const int b = z & 1;
    const float* Qb = qx + (size_t)b * SS * DD + h * DK;
    const float* Kb = kx + (size_t)b * SS * DD + h * DK;

    const int tid  = threadIdx.x;
    const int lane = tid & 31;
    const int warp = tid >> 5;
    const int wm   = (warp >> 2) * 32;   // 0 or 32
    const int wn   = (warp &  3) * 16;   // 0,16,32,48
    const int gid  = lane >> 2;
    const int tg   = lane & 3;
    const int row0 = blockIdx.y * 64;

    if (tid < 64) rowsum[tid] = 0.0f;

#pragma unroll
    for (int i = 0; i < 4; i++) {
        const int idx = tid + i * 256;      // 0..1023
        const int r   = idx >> 4;           // 0..63
        const int k4  = (idx & 15) * 4;     // 0..60
        float4 v = *(const float4*)&Qb[(size_t)(row0 + r) * DD + k4];
        *(uint4*)&Qs[r * 68 + k4] = make_uint4(f2tf32(v.x), f2tf32(v.y), f2tf32(v.z), f2tf32(v.w));
    }

    // preload K tile 0 into registers
    float4 kf[4];
#pragma unroll
    for (int i = 0; i < 4; i++) {
        const int idx = tid + i * 256;
        const int r   = idx >> 4;
        const int k4  = (idx & 15) * 4;
        kf[i] = *(const float4*)&Kb[(size_t)r * DD + k4];
    }

    for (int ct = 0; ct < SS / 64; ct++) {
        if (ct) __syncthreads();            // prev MMA reads of Ks done
#pragma unroll
        for (int i = 0; i < 4; i++) {
            const int idx = tid + i * 256;
            const int r   = idx >> 4;
            const int k4  = (idx & 15) * 4;
            *(uint4*)&Ks[r * 68 + k4] = make_uint4(f2tf32(kf[i].x), f2tf32(kf[i].y), f2tf32(kf[i].z), f2tf32(kf[i].w));
        }
        if (ct + 1 < SS / 64) {             // prefetch next K tile
#pragma unroll
            for (int i = 0; i < 4; i++) {
                const int idx = tid + i * 256;
                const int r   = idx >> 4;
                const int k4  = (idx & 15) * 4;
                kf[i] = *(const float4*)&Kb[(size_t)((ct + 1) * 64 + r) * DD + k4];
            }
        }
        __syncthreads();

        float acc[2][2][4] = {};
#pragma unroll
        for (int s = 0; s < 8; s++) {
            const int ko = s * 8;
            uint32_t a[2][4], bf[2][2];
#pragma unroll
            for (int mt = 0; mt < 2; mt++) {
                const uint32_t* base = &Qs[(wm + mt*16 + gid) * 68 + ko + tg];
                a[mt][0] = base[0];
                a[mt][1] = base[8*68];
                a[mt][2] = base[4];
                a[mt][3] = base[8*68 + 4];
            }
#pragma unroll
            for (int nt = 0; nt < 2; nt++) {
                const uint32_t* base = &Ks[(wn + nt*8 + gid) * 68 + ko + tg];
                bf[nt][0] = base[0];
                bf[nt][1] = base[4];
            }
#pragma unroll
            for (int mt = 0; mt < 2; mt++)
#pragma unroll
                for (int nt = 0; nt < 2; nt++)
                    mma_tf32(acc[mt][nt], a[mt], bf[nt]);
        }

#pragma unroll
        for (int mt = 0; mt < 2; mt++) {
            const int r1 = wm + mt*16 + gid;   // local row
            const int r2 = r1 + 8;
            float s1 = 0.0f, s2 = 0.0f;
#pragma unroll
            for (int nt = 0; nt < 2; nt++) {
                s1 += __expf(acc[mt][nt][0] * TEMP_INV) + __expf(acc[mt][nt][1] * TEMP_INV);
                s2 += __expf(acc[mt][nt][2] * TEMP_INV) + __expf(acc[mt][nt][3] * TEMP_INV);
            }
            s1 += __shfl_xor_sync(0xffffffffu, s1, 1);
            s1 += __shfl_xor_sync(0xffffffffu, s1, 2);
            s2 += __shfl_xor_sync(0xffffffffu, s2, 1);
            s2 += __shfl_xor_sync(0xffffffffu, s2, 2);
            if (tg == 0) {
                atomicAdd(&rowsum[r1], s1);
                atomicAdd(&rowsum[r2], s2);
            }
        }
    }
    __syncthreads();
    if (tid < 64)
        stats[(size_t)z * SS + row0 + tid] = 1.0f / rowsum[tid];
}

// ---------------------------------------------------------------------------
// PASS B: score_av — recompute identical s, scale by known inv, write the
// NORMALIZED attn exactly once, stage P in smem (ALIASED onto Ks — Ks is
// dead after the QK MMA), fuse P@V into ctx.
// K tile prefetched one iter ahead; V loaded at iter top, stored mid-iter
// (latency hidden under QK+exp). Dynamic smem 53504 B.
// ---------------------------------------------------------------------------
#define SAV_SMEM_BYTES 53504
__global__ __launch_bounds__(256)
void score_av(const float* __restrict__ qx, const float* __restrict__ kx,
              const float* __restrict__ stats, const float* __restrict__ vx,
              float* __restrict__ attn, float* __restrict__ ctx)
{
    extern __shared__ uint32_t sm[];
    uint32_t* Qs  = sm;                  // 64*68 = 4352 words
    uint32_t* Ks  = sm + 4352;           // 4352 (Ps aliases this region)
    uint32_t* Ps  = sm + 4352;           // alias of Ks
    uint32_t* Vs  = sm + 8704;           // 64*72 = 4608
    float* inv_s  = (float*)(sm + 13312);// 64 words  (total 13376 w = 53504 B)

    const int z = blockIdx.z;
    const int h = z >> 1;
    const int b = z & 1;
    const float* Qb = qx + (size_t)b * SS * DD + h * DK;
    const float* Kb = kx + (size_t)b * SS * DD + h * DK;
    const float* Vb = vx + (size_t)b * SS * DD + h * DK;
    float* Ab = attn + (size_t)z * SS * SS;
    float* Cb = ctx + (size_t)b * SS * DD + h * DK;

    const int tid  = threadIdx.x;
    const int lane = tid & 31;
    const int warp = tid >> 5;
    const int wm   = (warp >> 2) * 32;   // 0 or 32
    const int wn   = (warp &  3) * 16;   // 0,16,32,48
    const int gid  = lane >> 2;
    const int tg   = lane & 3;
    const int row0 = blockIdx.y * 64;

    // load Q strip + inv
#pragma unroll
    for (int i = 0; i < 4; i++) {
        const int idx = tid + i * 256;
        const int r   = idx >> 4;
        const int k4  = (idx & 15) * 4;
        float4 v = *(const float4*)&Qb[(size_t)(row0 + r) * DD + k4];
        *(uint4*)&Qs[r * 68 + k4] = make_uint4(f2tf32(v.x), f2tf32(v.y), f2tf32(v.z), f2tf32(v.w));
    }
    if (tid < 64) inv_s[tid] = stats[(size_t)z * SS + row0 + tid];

    // preload K tile 0
    float4 kf[4];
#pragma unroll
    for (int i = 0; i < 4; i++) {
        const int idx = tid + i * 256;
        const int r   = idx >> 4;
        const int k4  = (idx & 15) * 4;
        kf[i] = *(const float4*)&Kb[(size_t)r * DD + k4];
    }

    float cacc[2][2][4] = {};

    for (int ct = 0; ct < SS / 64; ct++) {
        if (ct) __syncthreads();   // prev AV reads of Ps(=Ks) & Vs done
        // store K tile (from prefetch regs)
#pragma unroll
        for (int i = 0; i < 4; i++) {
            const int idx = tid + i * 256;
            const int r   = idx >> 4;
            const int k4  = (idx & 15) * 4;
            *(uint4*)&Ks[r * 68 + k4] = make_uint4(f2tf32(kf[i].x), f2tf32(kf[i].y), f2tf32(kf[i].z), f2tf32(kf[i].w));
        }
        // load V tile for THIS iter (consumed mid-iter, latency hidden)
        float4 vf[4];
#pragma unroll
        for (int i = 0; i < 4; i++) {
            const int idx = tid + i * 256;
            const int r   = idx >> 4;
            const int k4  = (idx & 15) * 4;
            vf[i] = *(const float4*)&Vb[(size_t)(ct * 64 + r) * DD + k4];
        }
        // prefetch K tile for NEXT iter
        if (ct + 1 < SS / 64) {
#pragma unroll
            for (int i = 0; i < 4; i++) {
                const int idx = tid + i * 256;
                const int r   = idx >> 4;
                const int k4  = (idx & 15) * 4;
                kf[i] = *(const float4*)&Kb[(size_t)((ct + 1) * 64 + r) * DD + k4];
            }
        }
        __syncthreads();   // Ks ready (ct=0: Qs/inv also)

        // QK^T (identical fragment/MMA order to row_sums -> identical s)
        float sacc[2][2][4] = {};
#pragma unroll
        for (int s = 0; s < 8; s++) {
            const int ko = s * 8;
            uint32_t a[2][4], bf[2][2];
#pragma unroll
            for (int mt = 0; mt < 2; mt++) {
                const uint32_t* base = &Qs[(wm + mt*16 + gid) * 68 + ko + tg];
                a[mt][0] = base[0];
                a[mt][1] = base[8*68];
                a[mt][2] = base[4];
                a[mt][3] = base[8*68 + 4];
            }
#pragma unroll
            for (int nt = 0; nt < 2; nt++) {
                const uint32_t* base = &Ks[(wn + nt*8 + gid) * 68 + ko + tg];
                bf[nt][0] = base[0];
                bf[nt][1] = base[4];
            }
#pragma unroll
            for (int mt = 0; mt < 2; mt++)
#pragma unroll
                for (int nt = 0; nt < 2; nt++)
                    mma_tf32(sacc[mt][nt], a[mt], bf[nt]);
        }

        // exp * inv -> normalized p; STG attn once (keep p in regs)
        float pv[2][2][4];
#pragma unroll
        for (int mt = 0; mt < 2; mt++) {
            const int r1 = wm + mt*16 + gid;
            const int r2 = r1 + 8;
            const float iv1 = inv_s[r1];
            const float iv2 = inv_s[r2];
#pragma unroll
            for (int nt = 0; nt < 2; nt++) {
                pv[mt][nt][0] = __expf(sacc[mt][nt][0] * TEMP_INV) * iv1;
                pv[mt][nt][1] = __expf(sacc[mt][nt][1] * TEMP_INV) * iv1;
                pv[mt][nt][2] = __expf(sacc[mt][nt][2] * TEMP_INV) * iv2;
                pv[mt][nt][3] = __expf(sacc[mt][nt][3] * TEMP_INV) * iv2;
                const int c = wn + nt*8 + tg*2;
                const int gc = ct * 64 + c;
                *(float2*)&Ab[(size_t)(row0 + r1) * SS + gc] = make_float2(pv[mt][nt][0], pv[mt][nt][1]);
                *(float2*)&Ab[(size_t)(row0 + r2) * SS + gc] = make_float2(pv[mt][nt][2], pv[mt][nt][3]);
            }
        }
        __syncthreads();   // all QK reads of Ks done -> safe to overwrite as Ps

        // stage P (into Ks region) and V tile
#pragma unroll
        for (int mt = 0; mt < 2; mt++) {
            const int r1 = wm + mt*16 + gid;
            const int r2 = r1 + 8;
#pragma unroll
            for (int nt = 0; nt < 2; nt++) {
                const int c = wn + nt*8 + tg*2;
                *(uint2*)&Ps[r1 * 68 + c] = make_uint2(f2tf32(pv[mt][nt][0]), f2tf32(pv[mt][nt][1]));
                *(uint2*)&Ps[r2 * 68 + c] = make_uint2(f2tf32(pv[mt][nt][2]), f2tf32(pv[mt][nt][3]));
            }
        }
#pragma unroll
        for (int i = 0; i < 4; i++) {
            const int idx = tid + i * 256;
            const int r   = idx >> 4;
            const int k4  = (idx & 15) * 4;
            *(uint4*)&Vs[r * 72 + k4] = make_uint4(f2tf32(vf[i].x), f2tf32(vf[i].y), f2tf32(vf[i].z), f2tf32(vf[i].w));
        }
        __syncthreads();   // Ps & Vs ready

        // AV: ctx += P(64q x 64k) @ V(64k x 64d); warp tile 32q x 16d
#pragma unroll
        for (int s = 0; s < 8; s++) {
            const int ko = s * 8;
            uint32_t a[2][4], bf[2][2];
#pragma unroll
            for (int mt = 0; mt < 2; mt++) {
                const uint32_t* base = &Ps[(wm + mt*16 + gid) * 68 + ko + tg];
                a[mt][0] = base[0];
                a[mt][1] = base[8*68];
                a[mt][2] = base[4];
                a[mt][3] = base[8*68 + 4];
            }
#pragma unroll
            for (int nt = 0; nt < 2; nt++) {
                const uint32_t* base = &Vs[(ko + tg) * 72 + wn + nt*8 + gid];
                bf[nt][0] = base[0];
                bf[nt][1] = base[4*72];
            }
#pragma unroll
            for (int mt = 0; mt < 2; mt++)
#pragma unroll
                for (int nt = 0; nt < 2; nt++)
                    mma_tf32(cacc[mt][nt], a[mt], bf[nt]);
        }
    }

    // write ctx
#pragma unroll
    for (int mt = 0; mt < 2; mt++) {
        const int r1 = row0 + wm + mt*16 + gid;
        const int r2 = r1 + 8;
#pragma unroll
        for (int nt = 0; nt < 2; nt++) {
            const int c = wn + nt*8 + tg*2;
            *(float2*)&Cb[(size_t)r1 * DD + c] = make_float2(cacc[mt][nt][0], cacc[mt][nt][1]);
            *(float2*)&Cb[(size_t)r2 * DD + c] = make_float2(cacc[mt][nt][2], cacc[mt][nt][3]);
        }
    }
}

// ---------------------------------------------------------------------------
// LayerNorm over last dim (1024). One block per row, warp-shuffle reductions.
// ---------------------------------------------------------------------------
__global__ __launch_bounds__(256)
void ln_kernel(const float* __restrict__ x, const float* __restrict__ g,
               const float* __restrict__ bta, float* __restrict__ out)
{
    const float* p = x + (size_t)blockIdx.x * DD;
    float* o = out + (size_t)blockIdx.x * DD;
    const int t = threadIdx.x;
    const int lane = t & 31, warp = t >> 5;
    __shared__ float reds[8], redq[8];

    float v[4];
    {
        float4 v0 = *(const float4*)&p[t*4];
        v[0]=v0.x; v[1]=v0.y; v[2]=v0.z; v[3]=v0.w;
    }
    float s = v[0]+v[1]+v[2]+v[3];
    float sq = v[0]*v[0]+v[1]*v[1]+v[2]*v[2]+v[3]*v[3];
#pragma unroll
    for (int off = 16; off > 0; off >>= 1) {
        s  += __shfl_xor_sync(0xffffffffu, s,  off);
        sq += __shfl_xor_sync(0xffffffffu, sq, off);
    }
    if (lane == 0) { reds[warp] = s; redq[warp] = sq; }
    __syncthreads();
    s = 0.0f; sq = 0.0f;
#pragma unroll
    for (int w = 0; w < 8; w++) { s += reds[w]; sq += redq[w]; }

    const float mean = s * (1.0f / DD);
    const float var  = sq * (1.0f / DD) - mean * mean;
    const float inv  = rsqrtf(var + LN_EPS);

    float4 gv = *(const float4*)&g[t*4];
    float4 bv = *(const float4*)&bta[t*4];
    float4 ov;
    ov.x = (v[0] - mean) * inv * gv.x + bv.x;
    ov.y = (v[1] - mean) * inv * gv.y + bv.y;
    ov.z = (v[2] - mean) * inv * gv.z + bv.z;
    ov.w = (v[3] - mean) * inv * gv.w + bv.w;
    *(float4*)&o[t*4] = ov;
}

// ---------------------------------------------------------------------------
extern "C" void kernel_launch(void* const* d_in, const int* in_sizes, int n_in,
                              void* d_out, int out_size)
{
    const float* k    = (const float*)d_in[0];
    const float* q    = (const float*)d_in[1];
    const float* wkw  = (const float*)d_in[2];
    const float* wkb  = (const float*)d_in[3];
    const float* wqw  = (const float*)d_in[4];
    const float* wqb  = (const float*)d_in[5];
    const float* wvw  = (const float*)d_in[6];
    const float* wvb  = (const float*)d_in[7];
    const float* dw   = (const float*)d_in[8];
    const float* db   = (const float*)d_in[9];
    const float* lng  = (const float*)d_in[10];
    const float* lnb  = (const float*)d_in[11];

    float* out  = (float*)d_out;                       // [B, S, D]
    float* attn = out + (size_t)MM * DD;               // [H*B, S, S]

    float *p_kx, *p_qx, *p_vx, *p_ctx, *p_den, *p_st;
    cudaGetSymbolAddress((void**)&p_kx,  g_kx);
    cudaGetSymbolAddress((void**)&p_qx,  g_qx);
    cudaGetSymbolAddress((void**)&p_vx,  g_vx);
    cudaGetSymbolAddress((void**)&p_ctx, g_ctx);
    cudaGetSymbolAddress((void**)&p_den, g_den);
    cudaGetSymbolAddress((void**)&p_st,  g_stats);

    // Idempotent, capture-safe; no static guard (harness forbids them).
    cudaFuncSetAttribute(score_av, cudaFuncAttributeMaxDynamicSharedMemorySize,
                         SAV_SMEM_BYTES);

    dim3 gProj(DD / 128, MM / 128, 3);                 // 8 x 32 x 3 = 768 CTAs

    proj_tf32<<<gProj, 256>>>(k, q, wkw, wkb, wqw, wqb, wvw, wvb,
                              p_kx, p_qx, p_vx);

    row_sums<<<dim3(1, SS/64, HH*BB), 256>>>(p_qx, p_kx, p_st);
    score_av<<<dim3(1, SS/64, HH*BB), 256, SAV_SMEM_BYTES>>>(
        p_qx, p_kx, p_st, p_vx, attn, p_ctx);

    dense_tf32<<<dim3(DD/128, MM/128), 256>>>(p_ctx, dw, db, p_den);
    ln_kernel<<<MM, 256>>>(p_den, lng, lnb, out);
}

// round 17
// speedup vs baseline: 1.1979x; 1.0838x over previous
#include <cuda_runtime.h>
#include <math.h>
#include <stdint.h>

// Problem dims (fixed by the reference)
#define BB   2
#define SS   2048
#define DD   1024
#define HH   16
#define DK   64
#define MM   (BB*SS)            // 4096 rows
#define TEMP_INV (1.0f/32.0f)   // 1/sqrt(1024)
#define LN_EPS 1e-5f

// Scratch (allocation-free rule: __device__ globals)
__device__ float g_kx   [(size_t)MM*DD];
__device__ float g_qx   [(size_t)MM*DD];
__device__ float g_vx   [(size_t)MM*DD];
__device__ float g_ctx  [(size_t)MM*DD];
__device__ float g_den  [(size_t)MM*DD];
__device__ float g_stats[(size_t)HH*BB*SS];   // 1/rowsum per (z, qrow)

// ---------------------------------------------------------------------------
// TF32 helpers
// ---------------------------------------------------------------------------
__device__ __forceinline__ uint32_t f2tf32(float x) {
    uint32_t r;
    asm("cvt.rna.tf32.f32 %0, %1;" : "=r"(r) : "f"(x));
    return r;
}

__device__ __forceinline__ void mma_tf32(float (&d)[4], const uint32_t (&a)[4],
                                         const uint32_t (&b)[2]) {
    asm volatile(
        "mma.sync.aligned.m16n8k8.row.col.f32.tf32.tf32.f32 "
        "{%0,%1,%2,%3}, {%4,%5,%6,%7}, {%8,%9}, {%0,%1,%2,%3};\n"
        : "+f"(d[0]), "+f"(d[1]), "+f"(d[2]), "+f"(d[3])
        : "r"(a[0]), "r"(a[1]), "r"(a[2]), "r"(a[3]),
          "r"(b[0]), "r"(b[1]));
}

// m16n8k8 fragment map (row.col), gid = lane>>2, tg = lane&3:
//  A: a0=(gid,tg) a1=(gid+8,tg) a2=(gid,tg+4) a3=(gid+8,tg+4)   [row=m,col=k]
//  B: b0=(k=tg, n=gid) b1=(k=tg+4, n=gid)
//  C: c0=(gid, tg*2) c1=(gid, tg*2+1) c2=(gid+8, tg*2) c3=(gid+8, tg*2+1)

// ---------------------------------------------------------------------------
// Core 128x128 TF32 GEMM body (measured-best: dense 85.9us, tensor 32.7%).
// ---------------------------------------------------------------------------
template <bool RELU>
__device__ __forceinline__
void gemm_body(const float* __restrict__ A, const float* __restrict__ W,
               const float* __restrict__ bias, float* __restrict__ C,
               int Ndim, int Kdim, int row0, int col0,
               uint32_t (*As)[128*20], uint32_t (*Bs)[128*20])
{
    const int tid  = threadIdx.x;
    const int lane = tid & 31;
    const int warp = tid >> 5;
    const int wm   = (warp >> 2) * 64;   // 0 or 64
    const int wn   = (warp &  3) * 32;   // 0,32,64,96
    const int gid  = lane >> 2;
    const int tg   = lane & 3;

    float acc[4][4][4] = {};

    float4 pa[2], pb[2];
#pragma unroll
    for (int i = 0; i < 2; i++) {
        const int idx = tid + i * 256;        // 0..511
        const int r   = idx >> 2;             // 0..127
        const int k4  = (idx & 3) * 4;        // 0,4,8,12
        pa[i] = *(const float4*)&A[(size_t)(row0 + r) * Kdim + k4];
        pb[i] = *(const float4*)&W[(size_t)(col0 + r) * Kdim + k4];
    }
#pragma unroll
    for (int i = 0; i < 2; i++) {
        const int idx = tid + i * 256;
        const int r   = idx >> 2;
        const int k4  = (idx & 3) * 4;
        *(uint4*)&As[0][r * 20 + k4] = make_uint4(f2tf32(pa[i].x), f2tf32(pa[i].y), f2tf32(pa[i].z), f2tf32(pa[i].w));
        *(uint4*)&Bs[0][r * 20 + k4] = make_uint4(f2tf32(pb[i].x), f2tf32(pb[i].y), f2tf32(pb[i].z), f2tf32(pb[i].w));
    }
    __syncthreads();

    int p = 0;
    for (int k0 = 0; k0 < Kdim; k0 += 16) {
        const bool more = (k0 + 16 < Kdim);
        if (more) {
#pragma unroll
            for (int i = 0; i < 2; i++) {
                const int idx = tid + i * 256;
                const int r   = idx >> 2;
                const int k4  = (idx & 3) * 4;
                pa[i] = *(const float4*)&A[(size_t)(row0 + r) * Kdim + k0 + 16 + k4];
                pb[i] = *(const float4*)&W[(size_t)(col0 + r) * Kdim + k0 + 16 + k4];
            }
        }
#pragma unroll
        for (int s = 0; s < 2; s++) {
            const int ko = s * 8;
            uint32_t a[4][4], b[4][2];
#pragma unroll
            for (int mt = 0; mt < 4; mt++) {
                const uint32_t* base = &As[p][(wm + mt*16 + gid) * 20 + ko + tg];
                a[mt][0] = base[0];
                a[mt][1] = base[8*20];
                a[mt][2] = base[4];
                a[mt][3] = base[8*20 + 4];
            }
#pragma unroll
            for (int nt = 0; nt < 4; nt++) {
                const uint32_t* base = &Bs[p][(wn + nt*8 + gid) * 20 + ko + tg];
                b[nt][0] = base[0];
                b[nt][1] = base[4];
            }
#pragma unroll
            for (int mt = 0; mt < 4; mt++)
#pragma unroll
                for (int nt = 0; nt < 4; nt++)
                    mma_tf32(acc[mt][nt], a[mt], b[nt]);
        }
        if (more) {
            const int q = p ^ 1;
#pragma unroll
            for (int i = 0; i < 2; i++) {
                const int idx = tid + i * 256;
                const int r   = idx >> 2;
                const int k4  = (idx & 3) * 4;
                *(uint4*)&As[q][r * 20 + k4] = make_uint4(f2tf32(pa[i].x), f2tf32(pa[i].y), f2tf32(pa[i].z), f2tf32(pa[i].w));
                *(uint4*)&Bs[q][r * 20 + k4] = make_uint4(f2tf32(pb[i].x), f2tf32(pb[i].y), f2tf32(pb[i].z), f2tf32(pb[i].w));
            }
            __syncthreads();
            p = q;
        }
    }

#pragma unroll
    for (int mt = 0; mt < 4; mt++) {
        const int r1 = row0 + wm + mt*16 + gid;
        const int r2 = r1 + 8;
#pragma unroll
        for (int nt = 0; nt < 4; nt++) {
            const int c = col0 + wn + nt*8 + tg*2;
            const float b0 = bias[c], b1 = bias[c+1];
            float2 v1 = make_float2(acc[mt][nt][0] + b0, acc[mt][nt][1] + b1);
            float2 v2 = make_float2(acc[mt][nt][2] + b0, acc[mt][nt][3] + b1);
            if (RELU) {
                v1.x = fmaxf(v1.x, 0.f); v1.y = fmaxf(v1.y, 0.f);
                v2.x = fmaxf(v2.x, 0.f); v2.y = fmaxf(v2.y, 0.f);
            }
            *(float2*)&C[(size_t)r1 * Ndim + c] = v1;
            *(float2*)&C[(size_t)r2 * Ndim + c] = v2;
        }
    }
}

// ---------------------------------------------------------------------------
// All three projections in ONE launch: blockIdx.z selects {K,Q,V}.
// ---------------------------------------------------------------------------
__global__ __launch_bounds__(256)
void proj_tf32(const float* __restrict__ k, const float* __restrict__ q,
               const float* __restrict__ wkw, const float* __restrict__ wkb,
               const float* __restrict__ wqw, const float* __restrict__ wqb,
               const float* __restrict__ wvw, const float* __restrict__ wvb,
               float* __restrict__ kx, float* __restrict__ qx,
               float* __restrict__ vx)
{
    __shared__ uint32_t As[2][128*20];
    __shared__ uint32_t Bs[2][128*20];

    const int zz = blockIdx.z;
    const float* A    = (zz == 1) ? q   : k;
    const float* W    = (zz == 0) ? wkw : (zz == 1) ? wqw : wvw;
    const float* bias = (zz == 0) ? wkb : (zz == 1) ? wqb : wvb;
    float*       C    = (zz == 0) ? kx  : (zz == 1) ? qx  : vx;

    gemm_body<false>(A, W, bias, C, DD, DD,
                     blockIdx.y * 128, blockIdx.x * 128, As, Bs);
}

// ---------------------------------------------------------------------------
// Dense + ReLU (single GEMM).
// ---------------------------------------------------------------------------
__global__ __launch_bounds__(256)
void dense_tf32(const float* __restrict__ A, const float* __restrict__ W,
                const float* __restrict__ bias, float* __restrict__ C)
{
    __shared__ uint32_t As[2][128*20];
    __shared__ uint32_t Bs[2][128*20];
    gemm_body<true>(A, W, bias, C, DD, DD,
                    blockIdx.y * 128, blockIdx.x * 128, As, Bs);
}

// ---------------------------------------------------------------------------
// PASS A: row_sums — widened key tile (128 keys/iter, warp tile 32x32,
// mt=2/nt=4 -> 2.0 LDS/MMA; 16 iterations). Dynamic smem 52480 B.
// ---------------------------------------------------------------------------
#define RS_SMEM_BYTES 52480
__global__ __launch_bounds__(256)
void row_sums(const float* __restrict__ qx, const float* __restrict__ kx,
              float* __restrict__ stats)
{
    extern __shared__ uint32_t smr[];
    uint32_t* Qs = smr;                   // 64*68  = 4352 words
    uint32_t* Ks = smr + 4352;            // 128*68 = 8704 words
    float* rowsum = (float*)(smr + 13056);// 64 words (total 13120 w = 52480 B)

    const int z = blockIdx.z;
    const int h = z >> 1;             // B == 2
    const int b = z & 1;
    const float* Qb = qx + (size_t)b * SS * DD + h * DK;
    const float* Kb = kx + (size_t)b * SS * DD + h * DK;

    const int tid  = threadIdx.x;
    const int lane = tid & 31;
    const int warp = tid >> 5;
    const int wm   = (warp >> 2) * 32;   // 0 or 32
    const int wn   = (warp &  3) * 32;   // 0,32,64,96
    const int gid  = lane >> 2;
    const int tg   = lane & 3;
    const int row0 = blockIdx.y * 64;

    if (tid < 64) rowsum[tid] = 0.0f;

#pragma unroll
    for (int i = 0; i < 4; i++) {
        const int idx = tid + i * 256;      // 0..1023
        const int r   = idx >> 4;           // 0..63
        const int k4  = (idx & 15) * 4;     // 0..60
        float4 v = *(const float4*)&Qb[(size_t)(row0 + r) * DD + k4];
        *(uint4*)&Qs[r * 68 + k4] = make_uint4(f2tf32(v.x), f2tf32(v.y), f2tf32(v.z), f2tf32(v.w));
    }
    __syncthreads();

    for (int kt = 0; kt < SS / 128; kt++) {
        if (kt) __syncthreads();            // prev MMA reads of Ks done
#pragma unroll
        for (int i = 0; i < 8; i++) {
            const int idx = tid + i * 256;  // 0..2047
            const int r   = idx >> 4;       // 0..127
            const int k4  = (idx & 15) * 4;
            float4 v = *(const float4*)&Kb[(size_t)(kt * 128 + r) * DD + k4];
            *(uint4*)&Ks[r * 68 + k4] = make_uint4(f2tf32(v.x), f2tf32(v.y), f2tf32(v.z), f2tf32(v.w));
        }
        __syncthreads();

        float acc[2][4][4] = {};
#pragma unroll
        for (int s = 0; s < 8; s++) {
            const int ko = s * 8;
            uint32_t a[2][4], bf[4][2];
#pragma unroll
            for (int mt = 0; mt < 2; mt++) {
                const uint32_t* base = &Qs[(wm + mt*16 + gid) * 68 + ko + tg];
                a[mt][0] = base[0];
                a[mt][1] = base[8*68];
                a[mt][2] = base[4];
                a[mt][3] = base[8*68 + 4];
            }
#pragma unroll
            for (int nt = 0; nt < 4; nt++) {
                const uint32_t* base = &Ks[(wn + nt*8 + gid) * 68 + ko + tg];
                bf[nt][0] = base[0];
                bf[nt][1] = base[4];
            }
#pragma unroll
            for (int mt = 0; mt < 2; mt++)
#pragma unroll
                for (int nt = 0; nt < 4; nt++)
                    mma_tf32(acc[mt][nt], a[mt], bf[nt]);
        }

#pragma unroll
        for (int mt = 0; mt < 2; mt++) {
            const int r1 = wm + mt*16 + gid;   // local row
            const int r2 = r1 + 8;
            float s1 = 0.0f, s2 = 0.0f;
#pragma unroll
            for (int nt = 0; nt < 4; nt++) {
                s1 += __expf(acc[mt][nt][0] * TEMP_INV) + __expf(acc[mt][nt][1] * TEMP_INV);
                s2 += __expf(acc[mt][nt][2] * TEMP_INV) + __expf(acc[mt][nt][3] * TEMP_INV);
            }
            s1 += __shfl_xor_sync(0xffffffffu, s1, 1);
            s1 += __shfl_xor_sync(0xffffffffu, s1, 2);
            s2 += __shfl_xor_sync(0xffffffffu, s2, 1);
            s2 += __shfl_xor_sync(0xffffffffu, s2, 2);
            if (tg == 0) {
                atomicAdd(&rowsum[r1], s1);
                atomicAdd(&rowsum[r2], s2);
            }
        }
    }
    __syncthreads();
    if (tid < 64)
        stats[(size_t)z * SS + row0 + tid] = 1.0f / rowsum[tid];
}

// ---------------------------------------------------------------------------
// PASS B: score_av — WIDENED to 128-key tiles matching row_sums.
// QK warp tile 32x32 (2.0 LDS/MMA); P staged into dead Ks region (stride
// 132 = 4 mod 32, conflict-free); AV consumes P(64x128) @ V(128x64).
// No K-prefetch regs (measured neutral in r15). Dynamic smem 89344 B.
// ---------------------------------------------------------------------------
#define SAV_SMEM_BYTES 89344
__global__ __launch_bounds__(256)
void score_av(const float* __restrict__ qx, const float* __restrict__ kx,
              const float* __restrict__ stats, const float* __restrict__ vx,
              float* __restrict__ attn, float* __restrict__ ctx)
{
    extern __shared__ uint32_t sm[];
    uint32_t* Qs  = sm;                   // 64*68  = 4352 words
    uint32_t* Ks  = sm + 4352;            // 128*68 = 8704 words (Ps aliases)
    uint32_t* Ps  = sm + 4352;            // 64*132 = 8448 <= 8704
    uint32_t* Vs  = sm + 13056;           // 128*72 = 9216 words
    float* inv_s  = (float*)(sm + 22272); // 64 words (total 22336 w = 89344 B)

    const int z = blockIdx.z;
    const int h = z >> 1;
    const int b = z & 1;
    const float* Qb = qx + (size_t)b * SS * DD + h * DK;
    const float* Kb = kx + (size_t)b * SS * DD + h * DK;
    const float* Vb = vx + (size_t)b * SS * DD + h * DK;
    float* Ab = attn + (size_t)z * SS * SS;
    float* Cb = ctx + (size_t)b * SS * DD + h * DK;

    const int tid  = threadIdx.x;
    const int lane = tid & 31;
    const int warp = tid >> 5;
    const int wm   = (warp >> 2) * 32;   // 0 or 32
    const int wnq  = (warp &  3) * 32;   // QK: 0,32,64,96 (128 keys)
    const int wnd  = (warp &  3) * 16;   // AV: 0,16,32,48 (64 dims)
    const int gid  = lane >> 2;
    const int tg   = lane & 3;
    const int row0 = blockIdx.y * 64;

    // load Q strip + inv
#pragma unroll
    for (int i = 0; i < 4; i++) {
        const int idx = tid + i * 256;
        const int r   = idx >> 4;
        const int k4  = (idx & 15) * 4;
        float4 v = *(const float4*)&Qb[(size_t)(row0 + r) * DD + k4];
        *(uint4*)&Qs[r * 68 + k4] = make_uint4(f2tf32(v.x), f2tf32(v.y), f2tf32(v.z), f2tf32(v.w));
    }
    if (tid < 64) inv_s[tid] = stats[(size_t)z * SS + row0 + tid];
    __syncthreads();

    float cacc[2][2][4] = {};

    for (int kt = 0; kt < SS / 128; kt++) {
        if (kt) __syncthreads();   // prev AV reads of Ps(=Ks) & Vs done
        // stage K and V tiles (128 rows x 64 each; 8 float4/thread each)
#pragma unroll
        for (int i = 0; i < 8; i++) {
            const int idx = tid + i * 256;  // 0..2047
            const int r   = idx >> 4;       // 0..127
            const int k4  = (idx & 15) * 4;
            float4 kv = *(const float4*)&Kb[(size_t)(kt * 128 + r) * DD + k4];
            float4 vv = *(const float4*)&Vb[(size_t)(kt * 128 + r) * DD + k4];
            *(uint4*)&Ks[r * 68 + k4] = make_uint4(f2tf32(kv.x), f2tf32(kv.y), f2tf32(kv.z), f2tf32(kv.w));
            *(uint4*)&Vs[r * 72 + k4] = make_uint4(f2tf32(vv.x), f2tf32(vv.y), f2tf32(vv.z), f2tf32(vv.w));
        }
        __syncthreads();

        // QK^T: 64q x 128k, warp tile 32x32 (identical per-element chain to
        // row_sums -> bitwise-identical s -> exact normalization)
        float sacc[2][4][4] = {};
#pragma unroll
        for (int s = 0; s < 8; s++) {
            const int ko = s * 8;
            uint32_t a[2][4], bf[4][2];
#pragma unroll
            for (int mt = 0; mt < 2; mt++) {
                const uint32_t* base = &Qs[(wm + mt*16 + gid) * 68 + ko + tg];
                a[mt][0] = base[0];
                a[mt][1] = base[8*68];
                a[mt][2] = base[4];
                a[mt][3] = base[8*68 + 4];
            }
#pragma unroll
            for (int nt = 0; nt < 4; nt++) {
                const uint32_t* base = &Ks[(wnq + nt*8 + gid) * 68 + ko + tg];
                bf[nt][0] = base[0];
                bf[nt][1] = base[4];
            }
#pragma unroll
            for (int mt = 0; mt < 2; mt++)
#pragma unroll
                for (int nt = 0; nt < 4; nt++)
                    mma_tf32(sacc[mt][nt], a[mt], bf[nt]);
        }

        // p = exp(s/32)*inv (in place over sacc); STG normalized attn once
#pragma unroll
        for (int mt = 0; mt < 2; mt++) {
            const int r1 = wm + mt*16 + gid;
            const int r2 = r1 + 8;
            const float iv1 = inv_s[r1];
            const float iv2 = inv_s[r2];
#pragma unroll
            for (int nt = 0; nt < 4; nt++) {
                sacc[mt][nt][0] = __expf(sacc[mt][nt][0] * TEMP_INV) * iv1;
                sacc[mt][nt][1] = __expf(sacc[mt][nt][1] * TEMP_INV) * iv1;
                sacc[mt][nt][2] = __expf(sacc[mt][nt][2] * TEMP_INV) * iv2;
                sacc[mt][nt][3] = __expf(sacc[mt][nt][3] * TEMP_INV) * iv2;
                const int c  = wnq + nt*8 + tg*2;
                const int gc = kt * 128 + c;
                *(float2*)&Ab[(size_t)(row0 + r1) * SS + gc] = make_float2(sacc[mt][nt][0], sacc[mt][nt][1]);
                *(float2*)&Ab[(size_t)(row0 + r2) * SS + gc] = make_float2(sacc[mt][nt][2], sacc[mt][nt][3]);
            }
        }
        __syncthreads();   // QK reads of Ks done -> safe to overwrite as Ps

        // stage P (64 rows x 128 cols, stride 132) into the Ks region
#pragma unroll
        for (int mt = 0; mt < 2; mt++) {
            const int r1 = wm + mt*16 + gid;
            const int r2 = r1 + 8;
#pragma unroll
            for (int nt = 0; nt < 4; nt++) {
                const int c = wnq + nt*8 + tg*2;
                *(uint2*)&Ps[r1 * 132 + c] = make_uint2(f2tf32(sacc[mt][nt][0]), f2tf32(sacc[mt][nt][1]));
                *(uint2*)&Ps[r2 * 132 + c] = make_uint2(f2tf32(sacc[mt][nt][2]), f2tf32(sacc[mt][nt][3]));
            }
        }
        __syncthreads();   // Ps ready (Vs already ready since tile staging)

        // AV: ctx += P(64q x 128k) @ V(128k x 64d); warp tile 32q x 16d
#pragma unroll
        for (int s = 0; s < 16; s++) {
            const int ko = s * 8;
            uint32_t a[2][4], bf[2][2];
#pragma unroll
            for (int mt = 0; mt < 2; mt++) {
                const uint32_t* base = &Ps[(wm + mt*16 + gid) * 132 + ko + tg];
                a[mt][0] = base[0];
                a[mt][1] = base[8*132];
                a[mt][2] = base[4];
                a[mt][3] = base[8*132 + 4];
            }
#pragma unroll
            for (int nt = 0; nt < 2; nt++) {
                const uint32_t* base = &Vs[(ko + tg) * 72 + wnd + nt*8 + gid];
                bf[nt][0] = base[0];
                bf[nt][1] = base[4*72];
            }
#pragma unroll
            for (int mt = 0; mt < 2; mt++)
#pragma unroll
                for (int nt = 0; nt < 2; nt++)
                    mma_tf32(cacc[mt][nt], a[mt], bf[nt]);
        }
    }

    // write ctx
#pragma unroll
    for (int mt = 0; mt < 2; mt++) {
        const int r1 = row0 + wm + mt*16 + gid;
        const int r2 = r1 + 8;
#pragma unroll
        for (int nt = 0; nt < 2; nt++) {
            const int c = wnd + nt*8 + tg*2;
            *(float2*)&Cb[(size_t)r1 * DD + c] = make_float2(cacc[mt][nt][0], cacc[mt][nt][1]);
            *(float2*)&Cb[(size_t)r2 * DD + c] = make_float2(cacc[mt][nt][2], cacc[mt][nt][3]);
        }
    }
}

// ---------------------------------------------------------------------------
// LayerNorm over last dim (1024). One block per row, warp-shuffle reductions.
// ---------------------------------------------------------------------------
__global__ __launch_bounds__(256)
void ln_kernel(const float* __restrict__ x, const float* __restrict__ g,
               const float* __restrict__ bta, float* __restrict__ out)
{
    const float* p = x + (size_t)blockIdx.x * DD;
    float* o = out + (size_t)blockIdx.x * DD;
    const int t = threadIdx.x;
    const int lane = t & 31, warp = t >> 5;
    __shared__ float reds[8], redq[8];

    float v[4];
    {
        float4 v0 = *(const float4*)&p[t*4];
        v[0]=v0.x; v[1]=v0.y; v[2]=v0.z; v[3]=v0.w;
    }
    float s = v[0]+v[1]+v[2]+v[3];
    float sq = v[0]*v[0]+v[1]*v[1]+v[2]*v[2]+v[3]*v[3];
#pragma unroll
    for (int off = 16; off > 0; off >>= 1) {
        s  += __shfl_xor_sync(0xffffffffu, s,  off);
        sq += __shfl_xor_sync(0xffffffffu, sq, off);
    }
    if (lane == 0) { reds[warp] = s; redq[warp] = sq; }
    __syncthreads();
    s = 0.0f; sq = 0.0f;
#pragma unroll
    for (int w = 0; w < 8; w++) { s += reds[w]; sq += redq[w]; }

    const float mean = s * (1.0f / DD);
    const float var  = sq * (1.0f / DD) - mean * mean;
    const float inv  = rsqrtf(var + LN_EPS);

    float4 gv = *(const float4*)&g[t*4];
    float4 bv = *(const float4*)&bta[t*4];
    float4 ov;
    ov.x = (v[0] - mean) * inv * gv.x + bv.x;
    ov.y = (v[1] - mean) * inv * gv.y + bv.y;
    ov.z = (v[2] - mean) * inv * gv.z + bv.z;
    ov.w = (v[3] - mean) * inv * gv.w + bv.w;
    *(float4*)&o[t*4] = ov;
}

// ---------------------------------------------------------------------------
extern "C" void kernel_launch(void* const* d_in, const int* in_sizes, int n_in,
                              void* d_out, int out_size)
{
    const float* k    = (const float*)d_in[0];
    const float* q    = (const float*)d_in[1];
    const float* wkw  = (const float*)d_in[2];
    const float* wkb  = (const float*)d_in[3];
    const float* wqw  = (const float*)d_in[4];
    const float* wqb  = (const float*)d_in[5];
    const float* wvw  = (const float*)d_in[6];
    const float* wvb  = (const float*)d_in[7];
    const float* dw   = (const float*)d_in[8];
    const float* db   = (const float*)d_in[9];
    const float* lng  = (const float*)d_in[10];
    const float* lnb  = (const float*)d_in[11];

    float* out  = (float*)d_out;                       // [B, S, D]
    float* attn = out + (size_t)MM * DD;               // [H*B, S, S]

    float *p_kx, *p_qx, *p_vx, *p_ctx, *p_den, *p_st;
    cudaGetSymbolAddress((void**)&p_kx,  g_kx);
    cudaGetSymbolAddress((void**)&p_qx,  g_qx);
    cudaGetSymbolAddress((void**)&p_vx,  g_vx);
    cudaGetSymbolAddress((void**)&p_ctx, g_ctx);
    cudaGetSymbolAddress((void**)&p_den, g_den);
    cudaGetSymbolAddress((void**)&p_st,  g_stats);

    // Idempotent, capture-safe; no static guards (harness forbids them).
    cudaFuncSetAttribute(score_av, cudaFuncAttributeMaxDynamicSharedMemorySize,
                         SAV_SMEM_BYTES);
    cudaFuncSetAttribute(row_sums, cudaFuncAttributeMaxDynamicSharedMemorySize,
                         RS_SMEM_BYTES);

    dim3 gProj(DD / 128, MM / 128, 3);                 // 8 x 32 x 3 = 768 CTAs

    proj_tf32<<<gProj, 256>>>(k, q, wkw, wkb, wqw, wqb, wvw, wvb,
                              p_kx, p_qx, p_vx);

    row_sums<<<dim3(1, SS/64, HH*BB), 256, RS_SMEM_BYTES>>>(p_qx, p_kx, p_st);
    score_av<<<dim3(1, SS/64, HH*BB), 256, SAV_SMEM_BYTES>>>(
        p_qx, p_kx, p_st, p_vx, attn, p_ctx);

    dense_tf32<<<dim3(DD/128, MM/128), 256>>>(p_ctx, dw, db, p_den);
    ln_kernel<<<MM, 256>>>(p_den, lng, lnb, out);
}